// round 4
// baseline (speedup 1.0000x reference)
#include <cuda_runtime.h>
#include <math.h>

// ---------------------------------------------------------------------------
// OTDetLoss: focal cls loss + smooth-L1 reg + angle + aligned IoU + objectness
// fused into 3 small kernels feeding double accumulators.
// Accumulator indices: 0=cls_sum, 1=n_fg, 2=reg_sum, 3=ang_sum, 4=iou_sum, 5=obj_sum
// ---------------------------------------------------------------------------

__device__ double g_acc[6];

__global__ void zero_acc_kernel() {
    if (threadIdx.x < 6) g_acc[threadIdx.x] = 0.0;
}

__device__ __forceinline__ float warp_sum(float v) {
#pragma unroll
    for (int o = 16; o > 0; o >>= 1) v += __shfl_down_sync(0xFFFFFFFFu, v, o);
    return v;
}

__device__ __forceinline__ float smooth_l1(float x) {
    float d = fabsf(x);
    return (d < 1.0f) ? 0.5f * d * d : d - 0.5f;
}

// -------------------- Kernel A: focal classification loss -------------------
// grid over B*K*C/4 float4 elements of cls_logits. slot = g/15, cls = g%15.
__global__ void __launch_bounds__(256)
cls_kernel(const float4* __restrict__ logits4,
           const int* __restrict__ labels,
           int n4) {
    const int i = blockIdx.x * blockDim.x + threadIdx.x;
    float sum = 0.0f;
    if (i < n4) {
        float4 v = logits4[i];
        float vs[4] = {v.x, v.y, v.z, v.w};
        const int base = i * 4;
#pragma unroll
        for (int j = 0; j < 4; j++) {
            const int g    = base + j;
            const int slot = g / 15;               // C == 15 (constant fold)
            const int cls  = g - slot * 15;
            const int lab  = __ldg(&labels[slot]);
            const float l  = vs[j];
            const bool oh  = (cls == lab);

            const float em = expf(-fabsf(l));      // exp(-|l|), no overflow
            const float r  = 1.0f / (1.0f + em);
            const float p  = (l >= 0.0f) ? r : em * r;   // sigmoid(l), stable
            const float bce = fmaxf(l, 0.0f) - (oh ? l : 0.0f) + log1pf(em);
            const float pt  = oh ? p : (1.0f - p);
            const float at  = oh ? 0.25f : 0.75f;
            const float om  = 1.0f - pt;
            sum += at * om * om * bce;             // gamma = 2
        }
    }
    // block reduce
    __shared__ float sh[8];
    float w = warp_sum(sum);
    const int lane = threadIdx.x & 31, wid = threadIdx.x >> 5;
    if (lane == 0) sh[wid] = w;
    __syncthreads();
    if (wid == 0) {
        float t = (lane < (blockDim.x >> 5)) ? sh[lane] : 0.0f;
        t = warp_sum(t);
        if (lane == 0) atomicAdd(&g_acc[0], (double)t);
    }
}

// -------------------- Kernel B: per-slot reg / angle / iou / obj ------------
__global__ void __launch_bounds__(256)
slot_kernel(const float* __restrict__ centers,
            const float* __restrict__ wh,
            const float* __restrict__ ang,
            const float* __restrict__ conf,
            const float* __restrict__ tg,
            const int*   __restrict__ labels,
            const int*   __restrict__ img,
            int n) {
    float inv_s = 1.0f / 640.0f;
    if (img) {
        int v = *img;
        if (v > 0 && v < 100000) inv_s = 1.0f / (float)v;
    }

    const int i = blockIdx.x * blockDim.x + threadIdx.x;
    float nfg = 0.0f, reg = 0.0f, angl = 0.0f, iou = 0.0f, obj = 0.0f;
    if (i < n) {
        const int lab = labels[i];
        const float c = conf[i];
        const float logc  = fmaxf(logf(c),     -100.0f);
        const float log1c = fmaxf(log1pf(-c),  -100.0f);
        if (lab >= 0) {
            nfg = 1.0f;
            obj = logc;
            const float2 ct = *reinterpret_cast<const float2*>(&centers[2 * i]);
            const float2 sz = *reinterpret_cast<const float2*>(&wh[2 * i]);
            const float* t = &tg[5 * i];
            const float t0 = t[0], t1 = t[1], t2 = t[2], t3 = t[3], t4 = t[4];

            reg = smooth_l1((ct.x - t0) * inv_s) + smooth_l1((ct.y - t1) * inv_s)
                + smooth_l1((sz.x - t2) * inv_s) + smooth_l1((sz.y - t3) * inv_s);

            float sp, cp, sg, cg;
            sincosf(2.0f * ang[i], &sp, &cp);
            sincosf(2.0f * t4,     &sg, &cg);
            angl = smooth_l1(sp - sg) + smooth_l1(cp - cg);

            const float ix = fminf(ct.x + 0.5f * sz.x, t0 + 0.5f * t2)
                           - fmaxf(ct.x - 0.5f * sz.x, t0 - 0.5f * t2);
            const float iy = fminf(ct.y + 0.5f * sz.y, t1 + 0.5f * t3)
                           - fmaxf(ct.y - 0.5f * sz.y, t1 - 0.5f * t3);
            const float inter = fmaxf(ix, 0.0f) * fmaxf(iy, 0.0f);
            const float uni = sz.x * sz.y + t2 * t3 - inter + 1e-7f;
            iou = 1.0f - inter / uni;
        } else {
            obj = log1c;
        }
    }

    __shared__ float sh[5][8];
    float vals[5] = {nfg, reg, angl, iou, obj};
    const int lane = threadIdx.x & 31, wid = threadIdx.x >> 5;
#pragma unroll
    for (int q = 0; q < 5; q++) {
        float w = warp_sum(vals[q]);
        if (lane == 0) sh[q][wid] = w;
    }
    __syncthreads();
    if (wid == 0) {
#pragma unroll
        for (int q = 0; q < 5; q++) {
            float t = (lane < (blockDim.x >> 5)) ? sh[q][lane] : 0.0f;
            t = warp_sum(t);
            if (lane == 0) atomicAdd(&g_acc[q + 1], (double)t);
        }
    }
}

// -------------------- Kernel C: finalize -------------------------------------
__global__ void finalize_kernel(float* __restrict__ out, double denom_obj) {
    if (threadIdx.x == 0 && blockIdx.x == 0) {
        const double nfg = g_acc[1];
        const double nf  = nfg < 1.0 ? 1.0 : nfg;
        // weights: CLS=1, REG=5, ANG=1, IOU=2, OBJ=1
        const double total = g_acc[0] / nf
                           + 5.0 * g_acc[2] / nf
                           +       g_acc[3] / nf
                           + 2.0 * g_acc[4] / nf
                           -       g_acc[5] / denom_obj;
        out[0] = (float)total;
    }
}

extern "C" void kernel_launch(void* const* d_in, const int* in_sizes, int n_in,
                              void* d_out, int out_size) {
    // Input order (metadata): centers, wh, angles, cls_logits, conf,
    //                         slot_targets, slot_labels, fg_mask, img_size
    const float* centers = (const float*)d_in[0];
    const float* wh      = (const float*)d_in[1];
    const float* angles  = (const float*)d_in[2];
    const float* logits  = (const float*)d_in[3];
    const float* conf    = (const float*)d_in[4];
    const float* targets = (const float*)d_in[5];
    const int*   labels  = (const int*)  d_in[6];
    // d_in[7] = fg_mask (bool) — identical to (labels >= 0); deliberately unused.
    const int*   img     = (n_in > 8) ? (const int*)d_in[8] : nullptr;

    const int BK = in_sizes[0] / 2;          // 64 * 8400 = 537600
    const int NC = in_sizes[3];              // BK * 15   = 8064000
    const int n4 = NC / 4;                   // 2016000

    float* out = (float*)d_out;

    zero_acc_kernel<<<1, 32>>>();
    cls_kernel<<<(n4 + 255) / 256, 256>>>(
        (const float4*)logits, labels, n4);
    slot_kernel<<<(BK + 255) / 256, 256>>>(
        centers, wh, angles, conf, targets, labels, img, BK);
    finalize_kernel<<<1, 32>>>(out, (double)BK);
}

// round 5
// speedup vs baseline: 1.1182x; 1.1182x over previous
#include <cuda_runtime.h>
#include <math.h>

// ---------------------------------------------------------------------------
// OTDetLoss fully fused: focal cls + smooth-L1 reg + angle + aligned IoU + obj
// in ONE kernel launch. Last block finalizes and resets state (graph-replay
// deterministic).
// acc indices: 0=cls_sum, 1=n_fg, 2=reg_sum, 3=ang_sum, 4=iou_sum, 5=obj_sum
// ---------------------------------------------------------------------------

__device__ double        g_acc[6];   // zero at module load; reset by last block
__device__ unsigned int  g_cnt;      // ditto

__device__ __forceinline__ float warp_sum(float v) {
#pragma unroll
    for (int o = 16; o > 0; o >>= 1) v += __shfl_down_sync(0xFFFFFFFFu, v, o);
    return v;
}

__device__ __forceinline__ float smooth_l1(float x) {
    float d = fabsf(x);
    return (d < 1.0f) ? 0.5f * d * d : d - 0.5f;
}

__global__ void __launch_bounds__(512)
fused_loss_kernel(const float4* __restrict__ logits4,
                  const float*  __restrict__ centers,
                  const float*  __restrict__ wh,
                  const float*  __restrict__ ang,
                  const float*  __restrict__ conf,
                  const float*  __restrict__ tg,
                  const int*    __restrict__ labels,
                  const int*    __restrict__ img,
                  float*        __restrict__ out,
                  int n4, int bk, double denom_obj) {
    const int tid = blockIdx.x * blockDim.x + threadIdx.x;

    float acc[6] = {0.f, 0.f, 0.f, 0.f, 0.f, 0.f};

    if (tid < n4) {
        // ---------------- focal classification loss (4 logits / thread) -----
        float4 v = logits4[tid];
        float vs[4] = {v.x, v.y, v.z, v.w};
        const int base = tid * 4;
        float sum = 0.0f;
#pragma unroll
        for (int j = 0; j < 4; j++) {
            const int g    = base + j;
            const int slot = g / 15;                 // C == 15
            const int cls  = g - slot * 15;
            const int lab  = __ldg(&labels[slot]);
            const float l  = vs[j];
            const bool oh  = (cls == lab);

            const float em = expf(-fabsf(l));
            const float r  = 1.0f / (1.0f + em);
            const float p  = (l >= 0.0f) ? r : em * r;       // stable sigmoid
            const float bce = fmaxf(l, 0.0f) - (oh ? l : 0.0f) + log1pf(em);
            const float pt  = oh ? p : (1.0f - p);
            const float at  = oh ? 0.25f : 0.75f;
            const float om  = 1.0f - pt;
            sum += at * om * om * bce;                       // gamma = 2
        }
        acc[0] = sum;
    } else {
        const int i = tid - n4;
        if (i < bk) {
            // ---------------- per-slot reg / angle / iou / obj --------------
            float inv_s = 1.0f / 640.0f;
            if (img) {
                int vimg = *img;
                if (vimg > 0 && vimg < 100000) inv_s = 1.0f / (float)vimg;
            }
            const int lab = labels[i];
            const float c = conf[i];
            if (lab >= 0) {
                acc[1] = 1.0f;
                acc[5] = fmaxf(logf(c), -100.0f);
                const float2 ct = *reinterpret_cast<const float2*>(&centers[2 * i]);
                const float2 sz = *reinterpret_cast<const float2*>(&wh[2 * i]);
                const float* t = &tg[5 * i];
                const float t0 = t[0], t1 = t[1], t2 = t[2], t3 = t[3], t4 = t[4];

                acc[2] = smooth_l1((ct.x - t0) * inv_s) + smooth_l1((ct.y - t1) * inv_s)
                       + smooth_l1((sz.x - t2) * inv_s) + smooth_l1((sz.y - t3) * inv_s);

                float sp, cp, sg, cg;
                sincosf(2.0f * ang[i], &sp, &cp);
                sincosf(2.0f * t4,     &sg, &cg);
                acc[3] = smooth_l1(sp - sg) + smooth_l1(cp - cg);

                const float ix = fminf(ct.x + 0.5f * sz.x, t0 + 0.5f * t2)
                               - fmaxf(ct.x - 0.5f * sz.x, t0 - 0.5f * t2);
                const float iy = fminf(ct.y + 0.5f * sz.y, t1 + 0.5f * t3)
                               - fmaxf(ct.y - 0.5f * sz.y, t1 - 0.5f * t3);
                const float inter = fmaxf(ix, 0.0f) * fmaxf(iy, 0.0f);
                const float uni = sz.x * sz.y + t2 * t3 - inter + 1e-7f;
                acc[4] = 1.0f - inter / uni;
            } else {
                acc[5] = fmaxf(log1pf(-c), -100.0f);
            }
        }
    }

    // ---------------- block reduction (6 quantities) -------------------------
    __shared__ float sh[6][16];
    __shared__ float blk[6];
    const int lane = threadIdx.x & 31, wid = threadIdx.x >> 5;
#pragma unroll
    for (int q = 0; q < 6; q++) {
        float w = warp_sum(acc[q]);
        if (lane == 0) sh[q][wid] = w;
    }
    __syncthreads();
    if (wid == 0) {
#pragma unroll
        for (int q = 0; q < 6; q++) {
            float t = (lane < (blockDim.x >> 5)) ? sh[q][lane] : 0.0f;
            t = warp_sum(t);
            if (lane == 0) blk[q] = t;
        }
    }
    __syncthreads();

    // threads 0..5 push their quantity (skip zero partials → fewer atomics)
    if (threadIdx.x < 6) {
        float t = blk[threadIdx.x];
        if (t != 0.0f) atomicAdd(&g_acc[threadIdx.x], (double)t);
    }
    __syncthreads();

    // ---------------- last-block finalize + state reset ----------------------
    __shared__ bool is_last;
    if (threadIdx.x == 0) {
        __threadfence();
        unsigned int done = atomicAdd(&g_cnt, 1u);
        is_last = (done == gridDim.x - 1);
    }
    __syncthreads();
    if (is_last && threadIdx.x == 0) {
        volatile double* a = g_acc;
        const double nfg = a[1];
        const double nf  = nfg < 1.0 ? 1.0 : nfg;
        // weights: CLS=1, REG=5, ANG=1, IOU=2, OBJ=1
        const double total = a[0] / nf
                           + 5.0 * a[2] / nf
                           +       a[3] / nf
                           + 2.0 * a[4] / nf
                           -       a[5] / denom_obj;
        out[0] = (float)total;
        // reset for next graph replay (deterministic device state)
        g_acc[0] = 0.0; g_acc[1] = 0.0; g_acc[2] = 0.0;
        g_acc[3] = 0.0; g_acc[4] = 0.0; g_acc[5] = 0.0;
        g_cnt = 0u;
        __threadfence();
    }
}

extern "C" void kernel_launch(void* const* d_in, const int* in_sizes, int n_in,
                              void* d_out, int out_size) {
    // Input order: centers, wh, angles, cls_logits, conf,
    //              slot_targets, slot_labels, fg_mask, img_size
    const float* centers = (const float*)d_in[0];
    const float* wh      = (const float*)d_in[1];
    const float* angles  = (const float*)d_in[2];
    const float* logits  = (const float*)d_in[3];
    const float* conf    = (const float*)d_in[4];
    const float* targets = (const float*)d_in[5];
    const int*   labels  = (const int*)  d_in[6];
    const int*   img     = (n_in > 8) ? (const int*)d_in[8] : nullptr;

    const int BK = in_sizes[0] / 2;          // 537600
    const int NC = in_sizes[3];              // 8064000
    const int n4 = NC / 4;                   // 2016000

    const int total = n4 + BK;               // 2553600
    const int threads = 512;
    const int blocks = (total + threads - 1) / threads;

    fused_loss_kernel<<<blocks, threads>>>(
        (const float4*)logits, centers, wh, angles, conf, targets, labels, img,
        (float*)d_out, n4, BK, (double)BK);
}